// round 3
// baseline (speedup 1.0000x reference)
#include <cuda_runtime.h>

#define BATCH 4
#define S_LEN 2048
#define HDIM  1024
#define NHQ   16
#define NKV   4
#define HD    64
#define SCALE 0.125f

// ---------------- device scratch (no cudaMalloc allowed) ----------------
__device__ float g_Q[(size_t)BATCH * NHQ * S_LEN * HD];   // [b, h, s, d]
__device__ float g_K[(size_t)BATCH * NKV * S_LEN * HD];   // [b, kvh, s, d]
__device__ float g_V[(size_t)BATCH * NKV * S_LEN * HD];   // [b, kvh, s, d]
__device__ float g_attn[(size_t)BATCH * S_LEN * NHQ * HD]; // [b, s, h*HD]

// ---------------- generic 128x128x8 SGEMM, 256 threads, 8x8/thread ------
// scatter==1: C is [b, head, s, d] with given head count (QKV projections)
// scatter==0: C is plain row-major MxN (output projection)
__global__ __launch_bounds__(256) void sgemm_kernel(
    const float* __restrict__ A, const float* __restrict__ B,
    float* __restrict__ C, int M, int N, int K, int scatter, int heads)
{
    __shared__ float As[8][128];
    __shared__ float Bs[8][128];

    const int bm = blockIdx.y << 7;
    const int bn = blockIdx.x << 7;
    const int tid = threadIdx.x;
    const int ar = tid >> 1, ac = (tid & 1) << 2;   // A tile: 128 rows x 8 cols
    const int br = tid >> 5, bc = (tid & 31) << 2;  // B tile: 8 rows x 128 cols
    const int tx = tid & 15, ty = tid >> 4;

    float acc[8][8];
#pragma unroll
    for (int i = 0; i < 8; i++)
#pragma unroll
        for (int j = 0; j < 8; j++) acc[i][j] = 0.f;

    const float* Aptr = A + (size_t)(bm + ar) * K + ac;
    const float* Bptr = B + (size_t)br * N + bn + bc;

    float4 av = *(const float4*)(Aptr);
    float4 bv = *(const float4*)(Bptr);

    for (int k0 = 0; k0 < K; k0 += 8) {
        As[ac + 0][ar] = av.x; As[ac + 1][ar] = av.y;
        As[ac + 2][ar] = av.z; As[ac + 3][ar] = av.w;
        *(float4*)(&Bs[br][bc]) = bv;
        __syncthreads();

        if (k0 + 8 < K) {  // software pipeline: prefetch next tiles
            av = *(const float4*)(Aptr + k0 + 8);
            bv = *(const float4*)(Bptr + (size_t)(k0 + 8) * N);
        }

#pragma unroll
        for (int k = 0; k < 8; k++) {
            float a_reg[8], b_reg[8];
            *(float4*)(a_reg)     = *(const float4*)(&As[k][ty * 8]);
            *(float4*)(a_reg + 4) = *(const float4*)(&As[k][ty * 8 + 4]);
            *(float4*)(b_reg)     = *(const float4*)(&Bs[k][tx * 8]);
            *(float4*)(b_reg + 4) = *(const float4*)(&Bs[k][tx * 8 + 4]);
#pragma unroll
            for (int i = 0; i < 8; i++)
#pragma unroll
                for (int j = 0; j < 8; j++)
                    acc[i][j] += a_reg[i] * b_reg[j];
        }
        __syncthreads();
    }

#pragma unroll
    for (int i = 0; i < 8; i++) {
        const int rm = bm + ty * 8 + i;
        float4 lo = make_float4(acc[i][0], acc[i][1], acc[i][2], acc[i][3]);
        float4 hi = make_float4(acc[i][4], acc[i][5], acc[i][6], acc[i][7]);
        if (scatter) {
            const int b = rm >> 11;          // S_LEN = 2048
            const int s = rm & 2047;
            const int cb = bn + tx * 8;      // 8 cols stay within one head (64|8)
            const int head = cb >> 6;
            const int d = cb & 63;
            float* dst = C + (((size_t)(b * heads + head)) * S_LEN + s) * HD + d;
            *(float4*)dst = lo;
            *(float4*)(dst + 4) = hi;
        } else {
            float* dst = C + (size_t)rm * N + bn + tx * 8;
            *(float4*)dst = lo;
            *(float4*)(dst + 4) = hi;
        }
    }
}

// ---------------- RMSNorm + interleaved RoPE, one warp per (row of HD=64) --
__global__ __launch_bounds__(256) void norm_rope_kernel(
    float* __restrict__ X, const float* __restrict__ w,
    const float* __restrict__ cosb, const float* __restrict__ sinb, int rows)
{
    const int row = blockIdx.x * 8 + threadIdx.y;
    if (row >= rows) return;
    const int lane = threadIdx.x;
    const int s = row & (S_LEN - 1);

    float2 x = *(float2*)(X + (size_t)row * HD + lane * 2);
    float ssq = x.x * x.x + x.y * x.y;
#pragma unroll
    for (int m = 16; m; m >>= 1) ssq += __shfl_xor_sync(0xffffffffu, ssq, m);
    const float inv = rsqrtf(ssq * (1.0f / 64.0f) + 1e-6f);

    const float n0 = x.x * inv * w[lane * 2];
    const float n1 = x.y * inv * w[lane * 2 + 1];
    const float c0 = cosb[(size_t)s * HD + lane * 2];
    const float c1 = cosb[(size_t)s * HD + lane * 2 + 1];
    const float s0 = sinb[(size_t)s * HD + lane * 2];
    const float s1 = sinb[(size_t)s * HD + lane * 2 + 1];

    float2 o;
    o.x = n0 * c0 - n1 * s0;   // x[2i]*cos - x[2i+1]*sin
    o.y = n1 * c1 + n0 * s1;   // x[2i+1]*cos + x[2i]*sin
    *(float2*)(X + (size_t)row * HD + lane * 2) = o;
}

// ---------------- flash attention (causal, GQA), 64-row Q tile -----------
__global__ __launch_bounds__(256) void flash_kernel(
    const float* __restrict__ Q, const float* __restrict__ K,
    const float* __restrict__ V, float* __restrict__ O)
{
    __shared__ float QsT[64][64];   // transposed: QsT[d][r]
    __shared__ float KsT[64][64];   // transposed: KsT[d][c]; reused as Ps[r][k]
    __shared__ float Vs[64][64];    // row-major: Vs[k][d]
    float (*Ps)[64] = KsT;

    const int bh = blockIdx.y;
    const int b = bh >> 4, h = bh & 15, kvh = (bh & 15) >> 2;
    const int i0 = blockIdx.x << 6;
    const float* Qb = Q + ((size_t)(b * NHQ + h) * S_LEN + i0) * HD;
    const float* Kb = K + (size_t)(b * NKV + kvh) * S_LEN * HD;
    const float* Vb = V + (size_t)(b * NKV + kvh) * S_LEN * HD;

    const int tid = threadIdx.x;
    const int tx = tid & 15, ty = tid >> 4;
    const int r0 = ty << 2, c0 = tx << 2;

    // load Q tile transposed
    for (int idx = tid; idx < 1024; idx += 256) {
        const int r = idx >> 4, d = (idx & 15) << 2;
        float4 v = *(const float4*)(Qb + (size_t)r * HD + d);
        QsT[d][r] = v.x; QsT[d + 1][r] = v.y; QsT[d + 2][r] = v.z; QsT[d + 3][r] = v.w;
    }

    float m_i[4] = {-1e30f, -1e30f, -1e30f, -1e30f};
    float l_i[4] = {0.f, 0.f, 0.f, 0.f};
    float oa[4][4];
#pragma unroll
    for (int i = 0; i < 4; i++)
#pragma unroll
        for (int j = 0; j < 4; j++) oa[i][j] = 0.f;

    const int ntiles = blockIdx.x + 1;
    for (int t = 0; t < ntiles; t++) {
        const int j0 = t << 6;
        __syncthreads();  // previous PV reads of Ps/Vs done
        for (int idx = tid; idx < 1024; idx += 256) {
            const int r = idx >> 4, d = (idx & 15) << 2;
            float4 kv = *(const float4*)(Kb + (size_t)(j0 + r) * HD + d);
            KsT[d][r] = kv.x; KsT[d + 1][r] = kv.y; KsT[d + 2][r] = kv.z; KsT[d + 3][r] = kv.w;
            *(float4*)(&Vs[r][d]) = *(const float4*)(Vb + (size_t)(j0 + r) * HD + d);
        }
        __syncthreads();

        // scores: sc[i][j] = Q[r0+i] . K[c0+j]
        float sc[4][4];
#pragma unroll
        for (int i = 0; i < 4; i++)
#pragma unroll
            for (int j = 0; j < 4; j++) sc[i][j] = 0.f;
#pragma unroll 8
        for (int d = 0; d < 64; d++) {
            float4 aq = *(const float4*)(&QsT[d][r0]);
            float4 bk = *(const float4*)(&KsT[d][c0]);
            sc[0][0] += aq.x * bk.x; sc[0][1] += aq.x * bk.y; sc[0][2] += aq.x * bk.z; sc[0][3] += aq.x * bk.w;
            sc[1][0] += aq.y * bk.x; sc[1][1] += aq.y * bk.y; sc[1][2] += aq.y * bk.z; sc[1][3] += aq.y * bk.w;
            sc[2][0] += aq.z * bk.x; sc[2][1] += aq.z * bk.y; sc[2][2] += aq.z * bk.z; sc[2][3] += aq.z * bk.w;
            sc[3][0] += aq.w * bk.x; sc[3][1] += aq.w * bk.y; sc[3][2] += aq.w * bk.z; sc[3][3] += aq.w * bk.w;
        }
        __syncthreads();  // done reading KsT (about to overwrite with Ps)

        const bool diag = (t == (int)blockIdx.x);
#pragma unroll
        for (int i = 0; i < 4; i++) {
#pragma unroll
            for (int j = 0; j < 4; j++) {
                float s = sc[i][j] * SCALE;
                if (diag && (c0 + j > r0 + i)) s = -1e9f;   // causal mask (matches ref)
                sc[i][j] = s;
            }
            float mt = fmaxf(fmaxf(sc[i][0], sc[i][1]), fmaxf(sc[i][2], sc[i][3]));
            mt = fmaxf(mt, __shfl_xor_sync(0xffffffffu, mt, 8));
            mt = fmaxf(mt, __shfl_xor_sync(0xffffffffu, mt, 4));
            mt = fmaxf(mt, __shfl_xor_sync(0xffffffffu, mt, 2));
            mt = fmaxf(mt, __shfl_xor_sync(0xffffffffu, mt, 1));
            const float m_new = fmaxf(m_i[i], mt);
            const float corr = __expf(m_i[i] - m_new);
            m_i[i] = m_new;
            float ps = 0.f;
#pragma unroll
            for (int j = 0; j < 4; j++) {
                const float p = __expf(sc[i][j] - m_new);
                sc[i][j] = p;
                ps += p;
            }
            ps += __shfl_xor_sync(0xffffffffu, ps, 8);
            ps += __shfl_xor_sync(0xffffffffu, ps, 4);
            ps += __shfl_xor_sync(0xffffffffu, ps, 2);
            ps += __shfl_xor_sync(0xffffffffu, ps, 1);
            l_i[i] = l_i[i] * corr + ps;
#pragma unroll
            for (int j = 0; j < 4; j++) oa[i][j] *= corr;
            *(float4*)(&Ps[r0 + i][c0]) = *(float4*)(&sc[i][0]);
        }
        __syncthreads();  // Ps visible

        // O += P @ V
#pragma unroll 8
        for (int k = 0; k < 64; k++) {
            float4 vv = *(const float4*)(&Vs[k][c0]);
#pragma unroll
            for (int i = 0; i < 4; i++) {
                const float p = Ps[r0 + i][k];
                oa[i][0] += p * vv.x; oa[i][1] += p * vv.y;
                oa[i][2] += p * vv.z; oa[i][3] += p * vv.w;
            }
        }
    }

    // normalize + write to [b, s, h*HD + d]
#pragma unroll
    for (int i = 0; i < 4; i++) {
        const float inv = 1.0f / l_i[i];
        float* dst = O + ((size_t)b * S_LEN + i0 + r0 + i) * (NHQ * HD) + h * HD + c0;
        *(float4*)dst = make_float4(oa[i][0] * inv, oa[i][1] * inv,
                                    oa[i][2] * inv, oa[i][3] * inv);
    }
}

// ---------------- launch ----------------
extern "C" void kernel_launch(void* const* d_in, const int* in_sizes, int n_in,
                              void* d_out, int out_size)
{
    const float* X    = (const float*)d_in[0];  // hidden_states [B,S,H]
    // d_in[1] causal_mask: implied by causal structure, unused
    const float* cosb = (const float*)d_in[2];
    const float* sinb = (const float*)d_in[3];
    const float* Wq   = (const float*)d_in[4];
    const float* Wk   = (const float*)d_in[5];
    const float* Wv   = (const float*)d_in[6];
    const float* Wo   = (const float*)d_in[7];
    const float* qw   = (const float*)d_in[8];
    const float* kw   = (const float*)d_in[9];
    float* out = (float*)d_out;

    void *pQ, *pK, *pV, *pA;
    cudaGetSymbolAddress(&pQ, g_Q);
    cudaGetSymbolAddress(&pK, g_K);
    cudaGetSymbolAddress(&pV, g_V);
    cudaGetSymbolAddress(&pA, g_attn);

    const int M = BATCH * S_LEN;  // 8192

    // QKV projections with scatter into [b, head, s, d]
    sgemm_kernel<<<dim3(NHQ * HD / 128, M / 128), 256>>>(X, Wq, (float*)pQ, M, NHQ * HD, HDIM, 1, NHQ);
    sgemm_kernel<<<dim3(NKV * HD / 128, M / 128), 256>>>(X, Wk, (float*)pK, M, NKV * HD, HDIM, 1, NKV);
    sgemm_kernel<<<dim3(NKV * HD / 128, M / 128), 256>>>(X, Wv, (float*)pV, M, NKV * HD, HDIM, 1, NKV);

    // RMSNorm + RoPE on Q and K
    norm_rope_kernel<<<(BATCH * NHQ * S_LEN) / 8, dim3(32, 8)>>>((float*)pQ, qw, cosb, sinb, BATCH * NHQ * S_LEN);
    norm_rope_kernel<<<(BATCH * NKV * S_LEN) / 8, dim3(32, 8)>>>((float*)pK, kw, cosb, sinb, BATCH * NKV * S_LEN);

    // flash attention -> [b, s, h*HD]
    flash_kernel<<<dim3(S_LEN / 64, BATCH * NHQ), 256>>>((const float*)pQ, (const float*)pK, (const float*)pV, (float*)pA);

    // output projection
    sgemm_kernel<<<dim3(HDIM / 128, M / 128), 256>>>((const float*)pA, Wo, out, M, HDIM, HDIM, 0, 0);
}